// round 16
// baseline (speedup 1.0000x reference)
#include <cuda_runtime.h>
#include <cstdint>

#define B_ 2
#define T_ 2048
#define C_ 1024
#define H_ 16
#define D_ 64
#define M_ (B_*T_)   // 4096 rows

// Scratch (no allocations allowed — device globals)
__device__ float g_Q[B_*H_*T_*D_];
__device__ float g_K[B_*H_*T_*D_];
__device__ float g_V[B_*H_*T_*D_];
__device__ float g_A[M_*C_];

// ---------------------------------------------------------------------------
// GEMM engine v3: 128x64 CTA tile, 256 threads, 32 acc floats/thread.
// Per-thread micro-tile: rows {ty*4..+3, 64+ty*4..+3} x cols {tx*4..+3}.
// Double-buffered SMEM + unconditional register prefetch, one sync/k-block.
// Goal: regs <= 85 -> 3 CTAs/SM (24 warps) for issue-stall hiding.
// All locals unconditionally initialized; no inline asm (lmem/guard triggers).
// ---------------------------------------------------------------------------
#define GBK  16
#define SSTA 132   // A k-row stride (128 rows + pad)
#define SSTB 68    // B k-row stride (64 rows + pad)
#define NKB  (C_/GBK)   // 64

__device__ __forceinline__ void gemm_tile_compute64(
    const float* __restrict__ A, const float* __restrict__ Bw,
    int m0, int n0, float acc[2][4][4],
    float (*As)[GBK * SSTA], float (*Bs)[GBK * SSTB])
{
    const int tid = threadIdx.x;
    const int tx = tid & 15, ty = tid >> 4;
    // Loader geometry: A rows rowL,rowL+64 (2 float4); B row rowL (1 float4)
    const int rowL = tid >> 2;          // 0..63
    const int c4   = (tid & 3) * 4;     // 0,4,8,12
    const float* Ap0 = &A[(size_t)(m0 + rowL)      * C_ + c4];
    const float* Ap1 = &A[(size_t)(m0 + rowL + 64) * C_ + c4];
    const float* Bp0 = &Bw[(size_t)(n0 + rowL)      * C_ + c4];

    // Prologue: stage 0 (unconditional loads)
    float4 va0 = *(const float4*)(Ap0);
    float4 va1 = *(const float4*)(Ap1);
    float4 vb0 = *(const float4*)(Bp0);
    As[0][(c4+0)*SSTA + rowL] = va0.x; As[0][(c4+1)*SSTA + rowL] = va0.y;
    As[0][(c4+2)*SSTA + rowL] = va0.z; As[0][(c4+3)*SSTA + rowL] = va0.w;
    As[0][(c4+0)*SSTA + rowL+64] = va1.x; As[0][(c4+1)*SSTA + rowL+64] = va1.y;
    As[0][(c4+2)*SSTA + rowL+64] = va1.z; As[0][(c4+3)*SSTA + rowL+64] = va1.w;
    Bs[0][(c4+0)*SSTB + rowL] = vb0.x; Bs[0][(c4+1)*SSTB + rowL] = vb0.y;
    Bs[0][(c4+2)*SSTB + rowL] = vb0.z; Bs[0][(c4+3)*SSTB + rowL] = vb0.w;
    __syncthreads();

    for (int kb = 0; kb < NKB; kb++) {
        const int buf = kb & 1;
        const int nb  = buf ^ 1;
        // Unconditional prefetch (clamped last iteration: in-bounds re-read,
        // redundant store of identical data). No uninitialized locals.
        const int kn = (kb + 1 < NKB) ? (kb + 1) * GBK : kb * GBK;
        va0 = *(const float4*)(Ap0 + kn);
        va1 = *(const float4*)(Ap1 + kn);
        vb0 = *(const float4*)(Bp0 + kn);

        #pragma unroll
        for (int k = 0; k < GBK; k++) {
            // Conflict-free: consecutive float4s per half-warp; A broadcasts.
            float4 a0 = *(const float4*)&As[buf][k*SSTA + ty*4];
            float4 a1 = *(const float4*)&As[buf][k*SSTA + 64 + ty*4];
            float4 b0 = *(const float4*)&Bs[buf][k*SSTB + tx*4];
            acc[0][0][0] += a0.x*b0.x; acc[0][0][1] += a0.x*b0.y;
            acc[0][0][2] += a0.x*b0.z; acc[0][0][3] += a0.x*b0.w;
            acc[0][1][0] += a0.y*b0.x; acc[0][1][1] += a0.y*b0.y;
            acc[0][1][2] += a0.y*b0.z; acc[0][1][3] += a0.y*b0.w;
            acc[0][2][0] += a0.z*b0.x; acc[0][2][1] += a0.z*b0.y;
            acc[0][2][2] += a0.z*b0.z; acc[0][2][3] += a0.z*b0.w;
            acc[0][3][0] += a0.w*b0.x; acc[0][3][1] += a0.w*b0.y;
            acc[0][3][2] += a0.w*b0.z; acc[0][3][3] += a0.w*b0.w;
            acc[1][0][0] += a1.x*b0.x; acc[1][0][1] += a1.x*b0.y;
            acc[1][0][2] += a1.x*b0.z; acc[1][0][3] += a1.x*b0.w;
            acc[1][1][0] += a1.y*b0.x; acc[1][1][1] += a1.y*b0.y;
            acc[1][1][2] += a1.y*b0.z; acc[1][1][3] += a1.y*b0.w;
            acc[1][2][0] += a1.z*b0.x; acc[1][2][1] += a1.z*b0.y;
            acc[1][2][2] += a1.z*b0.z; acc[1][2][3] += a1.z*b0.w;
            acc[1][3][0] += a1.w*b0.x; acc[1][3][1] += a1.w*b0.y;
            acc[1][3][2] += a1.w*b0.z; acc[1][3][3] += a1.w*b0.w;
        }

        As[nb][(c4+0)*SSTA + rowL] = va0.x; As[nb][(c4+1)*SSTA + rowL] = va0.y;
        As[nb][(c4+2)*SSTA + rowL] = va0.z; As[nb][(c4+3)*SSTA + rowL] = va0.w;
        As[nb][(c4+0)*SSTA + rowL+64] = va1.x; As[nb][(c4+1)*SSTA + rowL+64] = va1.y;
        As[nb][(c4+2)*SSTA + rowL+64] = va1.z; As[nb][(c4+3)*SSTA + rowL+64] = va1.w;
        Bs[nb][(c4+0)*SSTB + rowL] = vb0.x; Bs[nb][(c4+1)*SSTB + rowL] = vb0.y;
        Bs[nb][(c4+2)*SSTB + rowL] = vb0.z; Bs[nb][(c4+3)*SSTB + rowL] = vb0.w;
        __syncthreads();
    }
}

// ---------------------------------------------------------------------------
// Kernel 1: QKV projection. z selects Q/K/V; x is the 64-wide n-tile (0..15).
// ---------------------------------------------------------------------------
__global__ __launch_bounds__(256) void qkv_gemm_kernel(
    const float* __restrict__ x,
    const float* __restrict__ Wq, const float* __restrict__ Wk,
    const float* __restrict__ Wv)
{
    __shared__ float As[2][GBK * SSTA];
    __shared__ float Bs[2][GBK * SSTB];
    const float* Bw = (blockIdx.z == 0) ? Wq : (blockIdx.z == 1) ? Wk : Wv;
    float* dst      = (blockIdx.z == 0) ? g_Q : (blockIdx.z == 1) ? g_K : g_V;

    const int m0 = blockIdx.y * 128, n0 = blockIdx.x * 64;
    float acc[2][4][4];
    #pragma unroll
    for (int q = 0; q < 2; q++)
        #pragma unroll
        for (int i = 0; i < 4; i++)
            #pragma unroll
            for (int j = 0; j < 4; j++) acc[q][i][j] = 0.f;

    gemm_tile_compute64(x, Bw, m0, n0, acc, As, Bs);

    const int tx = threadIdx.x & 15, ty = threadIdx.x >> 4;
    const int n = n0 + tx * 4;
    const int h = n >> 6, d = n & 63;
    #pragma unroll
    for (int q = 0; q < 2; q++) {
        #pragma unroll
        for (int i = 0; i < 4; i++) {
            const int m = m0 + q * 64 + ty * 4 + i;
            const int b = m >> 11, t = m & 2047;
            size_t idx = ((size_t)((b * H_ + h) * T_ + t)) * D_ + d;
            *(float4*)&dst[idx] = make_float4(
                acc[q][i][0], acc[q][i][1], acc[q][i][2], acc[q][i][3]);
        }
    }
}

// ---------------------------------------------------------------------------
// Kernel 2: causal flash attention (byte-identical to R15 — current best)
// ---------------------------------------------------------------------------
#define KST 68

__global__ __launch_bounds__(256) void flash_kernel()
{
    extern __shared__ float sm[];
    float* Qs  = sm;
    float* KsT = Qs + 64 * 64;
    float* Vs  = KsT + 64 * KST;
    float* Ps  = Vs + 64 * 64;

    const int bh = blockIdx.y;
    const int q0 = ((int)gridDim.x - 1 - (int)blockIdx.x) * 64;
    const float* Qg = g_Q + (size_t)bh * T_ * D_;
    const float* Kg = g_K + (size_t)bh * T_ * D_;
    const float* Vg = g_V + (size_t)bh * T_ * D_;

    const int tid = threadIdx.x, tx = tid & 15, ty = tid >> 4;

    const int rowK = tid & 63;
    const int cKb  = (tid >> 6) * 4;
    const int rowVb = tid >> 4;
    const int cV    = (tid & 15) * 4;

    #pragma unroll
    for (int rep = 0; rep < 4; rep++) {
        int f = tid + rep * 256;
        int row = f >> 4, c4 = (f & 15) * 4;
        float4 v = *(const float4*)&Qg[(size_t)(q0 + row) * D_ + c4];
        v.x *= 0.125f; v.y *= 0.125f; v.z *= 0.125f; v.w *= 0.125f;
        *(float4*)&Qs[row * 64 + c4] = v;
    }

    {
        float4 k0 = *(const float4*)&Kg[(size_t)rowK * D_ + cKb];
        float4 k1 = *(const float4*)&Kg[(size_t)rowK * D_ + cKb + 16];
        float4 k2 = *(const float4*)&Kg[(size_t)rowK * D_ + cKb + 32];
        float4 k3 = *(const float4*)&Kg[(size_t)rowK * D_ + cKb + 48];
        float4 v0 = *(const float4*)&Vg[(size_t)(rowVb)      * D_ + cV];
        float4 v1 = *(const float4*)&Vg[(size_t)(rowVb + 16) * D_ + cV];
        float4 v2 = *(const float4*)&Vg[(size_t)(rowVb + 32) * D_ + cV];
        float4 v3 = *(const float4*)&Vg[(size_t)(rowVb + 48) * D_ + cV];
        KsT[(cKb+0)*KST + rowK] = k0.x; KsT[(cKb+1)*KST + rowK] = k0.y;
        KsT[(cKb+2)*KST + rowK] = k0.z; KsT[(cKb+3)*KST + rowK] = k0.w;
        KsT[(cKb+16)*KST + rowK] = k1.x; KsT[(cKb+17)*KST + rowK] = k1.y;
        KsT[(cKb+18)*KST + rowK] = k1.z; KsT[(cKb+19)*KST + rowK] = k1.w;
        KsT[(cKb+32)*KST + rowK] = k2.x; KsT[(cKb+33)*KST + rowK] = k2.y;
        KsT[(cKb+34)*KST + rowK] = k2.z; KsT[(cKb+35)*KST + rowK] = k2.w;
        KsT[(cKb+48)*KST + rowK] = k3.x; KsT[(cKb+49)*KST + rowK] = k3.y;
        KsT[(cKb+50)*KST + rowK] = k3.z; KsT[(cKb+51)*KST + rowK] = k3.w;
        *(float4*)&Vs[(rowVb)      * 64 + cV] = v0;
        *(float4*)&Vs[(rowVb + 16) * 64 + cV] = v1;
        *(float4*)&Vs[(rowVb + 32) * 64 + cV] = v2;
        *(float4*)&Vs[(rowVb + 48) * 64 + cV] = v3;
    }
    __syncthreads();

    float m_i[4], l_i[4], acc[4][4];
    #pragma unroll
    for (int i = 0; i < 4; i++) {
        m_i[i] = -1e30f; l_i[i] = 0.f;
        #pragma unroll
        for (int j = 0; j < 4; j++) acc[i][j] = 0.f;
    }

    for (int kv0 = 0; kv0 <= q0; kv0 += 64) {
        const int kvn = (kv0 + 64 <= q0) ? (kv0 + 64) : kv0;
        float4 pk0 = *(const float4*)&Kg[(size_t)(kvn + rowK) * D_ + cKb];
        float4 pk1 = *(const float4*)&Kg[(size_t)(kvn + rowK) * D_ + cKb + 16];
        float4 pk2 = *(const float4*)&Kg[(size_t)(kvn + rowK) * D_ + cKb + 32];
        float4 pk3 = *(const float4*)&Kg[(size_t)(kvn + rowK) * D_ + cKb + 48];
        float4 pv0 = *(const float4*)&Vg[(size_t)(kvn + rowVb)      * D_ + cV];
        float4 pv1 = *(const float4*)&Vg[(size_t)(kvn + rowVb + 16) * D_ + cV];
        float4 pv2 = *(const float4*)&Vg[(size_t)(kvn + rowVb + 32) * D_ + cV];
        float4 pv3 = *(const float4*)&Vg[(size_t)(kvn + rowVb + 48) * D_ + cV];

        float s[4][4];
        #pragma unroll
        for (int i = 0; i < 4; i++)
            #pragma unroll
            for (int j = 0; j < 4; j++) s[i][j] = 0.f;

        #pragma unroll
        for (int d4 = 0; d4 < 64; d4 += 4) {
            float qreg[4][4];
            #pragma unroll
            for (int i = 0; i < 4; i++) {
                float4 t = *(const float4*)&Qs[(ty*4 + i) * 64 + d4];
                qreg[i][0]=t.x; qreg[i][1]=t.y; qreg[i][2]=t.z; qreg[i][3]=t.w;
            }
            #pragma unroll
            for (int dd = 0; dd < 4; dd++) {
                float4 kv = *(const float4*)&KsT[(d4 + dd) * KST + tx * 4];
                #pragma unroll
                for (int i = 0; i < 4; i++) {
                    s[i][0] += qreg[i][dd] * kv.x;
                    s[i][1] += qreg[i][dd] * kv.y;
                    s[i][2] += qreg[i][dd] * kv.z;
                    s[i][3] += qreg[i][dd] * kv.w;
                }
            }
        }

        if (kv0 == q0) {
            #pragma unroll
            for (int i = 0; i < 4; i++)
                #pragma unroll
                for (int j = 0; j < 4; j++)
                    if (tx * 4 + j > ty * 4 + i) s[i][j] = -1e30f;
        }

        #pragma unroll
        for (int i = 0; i < 4; i++) {
            float mloc = fmaxf(fmaxf(s[i][0], s[i][1]), fmaxf(s[i][2], s[i][3]));
            #pragma unroll
            for (int off = 8; off > 0; off >>= 1)
                mloc = fmaxf(mloc, __shfl_xor_sync(0xffffffffu, mloc, off));
            float mnew = fmaxf(m_i[i], mloc);
            float corr = __expf(m_i[i] - mnew);
            m_i[i] = mnew;
            float rs = 0.f;
            #pragma unroll
            for (int j = 0; j < 4; j++) {
                float p = __expf(s[i][j] - mnew);
                s[i][j] = p; rs += p;
            }
            #pragma unroll
            for (int off = 8; off > 0; off >>= 1)
                rs += __shfl_xor_sync(0xffffffffu, rs, off);
            l_i[i] = l_i[i] * corr + rs;
            #pragma unroll
            for (int j = 0; j < 4; j++) acc[i][j] *= corr;
            *(float4*)&Ps[(ty*4 + i) * 64 + tx * 4] =
                make_float4(s[i][0], s[i][1], s[i][2], s[i][3]);
        }
        __syncthreads();

        #pragma unroll
        for (int kv4 = 0; kv4 < 64; kv4 += 4) {
            float preg[4][4];
            #pragma unroll
            for (int i = 0; i < 4; i++) {
                float4 t = *(const float4*)&Ps[(ty*4 + i) * 64 + kv4];
                preg[i][0]=t.x; preg[i][1]=t.y; preg[i][2]=t.z; preg[i][3]=t.w;
            }
            #pragma unroll
            for (int kk = 0; kk < 4; kk++) {
                float4 v = *(const float4*)&Vs[(kv4 + kk) * 64 + tx * 4];
                #pragma unroll
                for (int i = 0; i < 4; i++) {
                    acc[i][0] += preg[i][kk] * v.x;
                    acc[i][1] += preg[i][kk] * v.y;
                    acc[i][2] += preg[i][kk] * v.z;
                    acc[i][3] += preg[i][kk] * v.w;
                }
            }
        }
        __syncthreads();

        KsT[(cKb+0)*KST + rowK] = pk0.x; KsT[(cKb+1)*KST + rowK] = pk0.y;
        KsT[(cKb+2)*KST + rowK] = pk0.z; KsT[(cKb+3)*KST + rowK] = pk0.w;
        KsT[(cKb+16)*KST + rowK] = pk1.x; KsT[(cKb+17)*KST + rowK] = pk1.y;
        KsT[(cKb+18)*KST + rowK] = pk1.z; KsT[(cKb+19)*KST + rowK] = pk1.w;
        KsT[(cKb+32)*KST + rowK] = pk2.x; KsT[(cKb+33)*KST + rowK] = pk2.y;
        KsT[(cKb+34)*KST + rowK] = pk2.z; KsT[(cKb+35)*KST + rowK] = pk2.w;
        KsT[(cKb+48)*KST + rowK] = pk3.x; KsT[(cKb+49)*KST + rowK] = pk3.y;
        KsT[(cKb+50)*KST + rowK] = pk3.z; KsT[(cKb+51)*KST + rowK] = pk3.w;
        *(float4*)&Vs[(rowVb)      * 64 + cV] = pv0;
        *(float4*)&Vs[(rowVb + 16) * 64 + cV] = pv1;
        *(float4*)&Vs[(rowVb + 32) * 64 + cV] = pv2;
        *(float4*)&Vs[(rowVb + 48) * 64 + cV] = pv3;
        __syncthreads();
    }

    const int b = bh >> 4, h = bh & 15;
    #pragma unroll
    for (int i = 0; i < 4; i++) {
        int q = q0 + ty * 4 + i;
        float inv = 1.0f / l_i[i];
        float4 o = make_float4(acc[i][0]*inv, acc[i][1]*inv, acc[i][2]*inv, acc[i][3]*inv);
        *(float4*)&g_A[((size_t)(b * T_ + q)) * C_ + h * D_ + tx * 4] = o;
    }
}

// ---------------------------------------------------------------------------
// Kernel 3: output projection + bias (engine v3)
// ---------------------------------------------------------------------------
__global__ __launch_bounds__(256) void outproj_kernel(
    const float* __restrict__ Wo, const float* __restrict__ bo,
    float* __restrict__ out)
{
    __shared__ float As[2][GBK * SSTA];
    __shared__ float Bs[2][GBK * SSTB];
    const int m0 = blockIdx.y * 128, n0 = blockIdx.x * 64;
    float acc[2][4][4];
    #pragma unroll
    for (int q = 0; q < 2; q++)
        #pragma unroll
        for (int i = 0; i < 4; i++)
            #pragma unroll
            for (int j = 0; j < 4; j++) acc[q][i][j] = 0.f;

    gemm_tile_compute64(g_A, Wo, m0, n0, acc, As, Bs);

    const int tx = threadIdx.x & 15, ty = threadIdx.x >> 4;
    const int n = n0 + tx * 4;
    float4 bias = *(const float4*)&bo[n];
    #pragma unroll
    for (int q = 0; q < 2; q++) {
        #pragma unroll
        for (int i = 0; i < 4; i++) {
            const int m = m0 + q * 64 + ty * 4 + i;
            *(float4*)&out[(size_t)m * C_ + n] = make_float4(
                acc[q][i][0] + bias.x, acc[q][i][1] + bias.y,
                acc[q][i][2] + bias.z, acc[q][i][3] + bias.w);
        }
    }
}

// ---------------------------------------------------------------------------
extern "C" void kernel_launch(void* const* d_in, const int* in_sizes, int n_in,
                              void* d_out, int out_size)
{
    const float* x  = (const float*)d_in[0];
    const float* Wq = (const float*)d_in[1];
    const float* Wk = (const float*)d_in[2];
    const float* Wv = (const float*)d_in[3];
    const float* Wo = (const float*)d_in[4];
    const float* bo = (const float*)d_in[5];
    float* out = (float*)d_out;

    const int FLASH_SMEM = (64*64 + 64*KST + 64*64 + 64*64) * 4;  // 66560 B
    cudaFuncSetAttribute(flash_kernel,
                         cudaFuncAttributeMaxDynamicSharedMemorySize, FLASH_SMEM);

    dim3 gq(C_ / 64, M_ / 128, 3);      // (16, 32, 3)
    qkv_gemm_kernel<<<gq, 256>>>(x, Wq, Wk, Wv);

    flash_kernel<<<dim3(T_ / 64, B_ * H_), 256, FLASH_SMEM>>>();

    dim3 go(C_ / 64, M_ / 128, 1);      // (16, 32)
    outproj_kernel<<<go, 256>>>(Wo, bo, out);
}